// round 6
// baseline (speedup 1.0000x reference)
#include <cuda_runtime.h>
#include <cuda_bf16.h>
#include <math.h>
#include <stdint.h>

// Problem constants
#define B_  2
#define S_  2048
#define H_  2048
#define NH_ 16
#define HD_ 128
#define ROWS_ (B_ * S_)        // 4096
#define QKV_N (3 * H_)         // 6144

// ---------------- scratch (static device globals; no allocation) ----------------
__device__ float g_qkv[(size_t)ROWS_ * QKV_N];            // [4096, 6144]
__device__ float g_q[(size_t)B_ * NH_ * S_ * HD_];        // [b,h,s,d] tf32-rounded
__device__ float g_k[(size_t)B_ * NH_ * S_ * HD_];        // [b,h,s,d] tf32-rounded
__device__ float g_v[(size_t)B_ * NH_ * S_ * HD_];        // [b,h,d,s] tf32-rounded
__device__ float g_ctx[(size_t)ROWS_ * H_];               // [b*s, h*d] tf32-rounded
__device__ float g_hid_tf[(size_t)ROWS_ * H_];            // tf32-rounded A
__device__ float g_wct[(size_t)QKV_N * H_];               // Wc^T [6144][2048] tf32
__device__ float g_wpt[(size_t)H_ * H_];                  // Wp^T [2048][2048] tf32

// ---------------- helpers ----------------
__device__ __forceinline__ uint32_t f2tf(float x) {
    uint32_t r;
    asm("cvt.rna.tf32.f32 %0, %1;" : "=r"(r) : "f"(x));
    return r;
}
__device__ __forceinline__ float f2tff(float x) { return __uint_as_float(f2tf(x)); }

__device__ __forceinline__ void mma_tf32(float* c, const uint32_t* a, const uint32_t* b) {
    asm volatile(
        "mma.sync.aligned.m16n8k8.row.col.f32.tf32.tf32.f32 "
        "{%0,%1,%2,%3}, {%4,%5,%6,%7}, {%8,%9}, {%0,%1,%2,%3};\n"
        : "+f"(c[0]), "+f"(c[1]), "+f"(c[2]), "+f"(c[3])
        : "r"(a[0]), "r"(a[1]), "r"(a[2]), "r"(a[3]),
          "r"(b[0]), "r"(b[1]));
}
__device__ __forceinline__ void ldsm4(uint32_t* r, uint32_t addr) {
    asm volatile("ldmatrix.sync.aligned.m8n8.x4.shared.b16 {%0,%1,%2,%3}, [%4];"
        : "=r"(r[0]), "=r"(r[1]), "=r"(r[2]), "=r"(r[3]) : "r"(addr));
}
__device__ __forceinline__ uint32_t smem_u32(const void* p) {
    return (uint32_t)__cvta_generic_to_shared(p);
}
__device__ __forceinline__ void cp16(uint32_t dst, const void* src) {
    asm volatile("cp.async.cg.shared.global [%0], [%1], 16;" :: "r"(dst), "l"(src));
}
__device__ __forceinline__ void cp_commit() {
    asm volatile("cp.async.commit_group;");
}
template<int N> __device__ __forceinline__ void cp_wait() {
    asm volatile("cp.async.wait_group %0;" :: "n"(N));
}

// ---------------- tf32 pre-round (elementwise) ----------------
__global__ __launch_bounds__(256) void to_tf32k(const float* __restrict__ in,
                                                float* __restrict__ out, int n4)
{
    int i = blockIdx.x * 256 + threadIdx.x;
    if (i < n4) {
        float4 v = ((const float4*)in)[i];
        v.x = f2tff(v.x); v.y = f2tff(v.y); v.z = f2tff(v.z); v.w = f2tff(v.w);
        ((float4*)out)[i] = v;
    }
}

// ---------------- weight transpose + round: in[K][N] -> out[N][K] ----------------
__global__ __launch_bounds__(256) void wtrans(
    const float* __restrict__ in, float* __restrict__ out, int K, int N)
{
    __shared__ float t[32][33];
    const int k0 = blockIdx.x * 32, n0 = blockIdx.y * 32;
    const int x = threadIdx.x, y = threadIdx.y;   // 32 x 8
#pragma unroll
    for (int i = 0; i < 32; i += 8)
        t[y + i][x] = in[(size_t)(k0 + y + i) * N + n0 + x];
    __syncthreads();
#pragma unroll
    for (int i = 0; i < 32; i += 8)
        out[(size_t)(n0 + y + i) * K + k0 + x] = f2tff(t[x][y + i]);
}

// ---------------- TF32 GEMM: C[M,N] = A[M,K] @ Bt[N,K]^T + bias ----------------
// CTA tile 128(M) x 256(N), BK=16, 256 threads (8 warps as 2m x 4n), warp m64 x n64.
// As: [4][128][20], Bs: [4][256][20] (both k-minor, pad to 20 words -> ldsm conflict-free).
#define GA_ST 2560            // 128*20 words
#define GB_ST 5120            // 256*20 words
#define G_ST  (GA_ST + GB_ST) // 7680 words per stage
#define GEMM_SMEM (4 * G_ST * 4)   // 122880 B

__global__ __launch_bounds__(256) void gemm_tf32(
    const float* __restrict__ A, const float* __restrict__ Bt,
    const float* __restrict__ bias, float* __restrict__ C,
    int M, int N, int K)
{
    extern __shared__ float gsm[];
    const uint32_t as_u = smem_u32(gsm);
    const uint32_t bs_u = as_u + GA_ST * 4;

    const int tid = threadIdx.x;
    const int bx = blockIdx.x, by = blockIdx.y;
    const int warp = tid >> 5, lane = tid & 31;
    const int wm = (warp & 1) * 64;       // 2 warps in m
    const int wn = (warp >> 1) * 64;      // 4 warps in n
    const int lr = lane >> 2;
    const int lc = lane & 3;

    // ldmatrix lane geometry
    const int la_m = lane & 15;
    const int la_k = (lane >> 4) << 2;
    const int lb_r = (lane & 7) + ((lane >> 4) << 3);
    const int lb_c = ((lane >> 3) & 1) << 2;

    const uint32_t a_lane = as_u + (uint32_t)(((wm + la_m) * 20 + la_k) * 4);
    const uint32_t b_lane = bs_u + (uint32_t)(((wn + lb_r) * 20 + lb_c) * 4);

    const float* Ab = A + (size_t)(by * 128) * K;
    const float* Bb = Bt + (size_t)(bx * 256) * K;

    const int KT = K >> 4;

    // fill one k16 tile into stage st: A 128x16 (512 float4), B 256x16 (1024 float4)
#define ISSUE_TILE(kt, st)                                                        \
    do {                                                                          \
        const float* Asrc = Ab + (kt) * 16;                                       \
        const float* Bsrc = Bb + (kt) * 16;                                       \
        uint32_t au = as_u + (uint32_t)((st) * G_ST * 4);                         \
        uint32_t bu = bs_u + (uint32_t)((st) * G_ST * 4);                         \
        _Pragma("unroll")                                                         \
        for (int i = 0; i < 2; i++) {                                             \
            int ch = tid + 256 * i;                                               \
            int r = ch >> 2, c = (ch & 3) << 2;                                   \
            cp16(au + (uint32_t)((r * 20 + c) * 4), Asrc + (size_t)r * K + c);    \
        }                                                                         \
        _Pragma("unroll")                                                         \
        for (int i = 0; i < 4; i++) {                                             \
            int ch = tid + 256 * i;                                               \
            int r = ch >> 2, c = (ch & 3) << 2;                                   \
            cp16(bu + (uint32_t)((r * 20 + c) * 4), Bsrc + (size_t)r * K + c);    \
        }                                                                         \
    } while (0)

    ISSUE_TILE(0, 0); cp_commit();
    ISSUE_TILE(1, 1); cp_commit();
    ISSUE_TILE(2, 2); cp_commit();

    float c[4][8][4];
#pragma unroll
    for (int mt = 0; mt < 4; mt++)
#pragma unroll
        for (int nt = 0; nt < 8; nt++)
#pragma unroll
            for (int j = 0; j < 4; j++) c[mt][nt][j] = 0.f;

    for (int kt = 0; kt < KT; kt++) {
        cp_wait<2>();
        __syncthreads();
        if (kt + 3 < KT) { ISSUE_TILE(kt + 3, (kt + 3) & 3); }
        cp_commit();

        const uint32_t stoff = (uint32_t)((kt & 3) * G_ST * 4);
        const uint32_t a_st = a_lane + stoff;
        const uint32_t b_st = b_lane + stoff;

#pragma unroll
        for (int ks = 0; ks < 2; ks++) {
            const int kb = ks * 8;
            uint32_t af[4][4], bf[8][2];
#pragma unroll
            for (int mt = 0; mt < 4; mt++)
                ldsm4(af[mt], a_st + (uint32_t)((mt * 16 * 20 + kb) * 4));
#pragma unroll
            for (int p = 0; p < 4; p++) {
                uint32_t r[4];
                ldsm4(r, b_st + (uint32_t)((p * 16 * 20 + kb) * 4));
                bf[2 * p][0] = r[0]; bf[2 * p][1] = r[1];
                bf[2 * p + 1][0] = r[2]; bf[2 * p + 1][1] = r[3];
            }
#pragma unroll
            for (int mt = 0; mt < 4; mt++)
#pragma unroll
                for (int nt = 0; nt < 8; nt++)
                    mma_tf32(c[mt][nt], af[mt], bf[nt]);
        }
    }
#undef ISSUE_TILE

    // epilogue
#pragma unroll
    for (int mt = 0; mt < 4; mt++) {
        int row = by * 128 + wm + mt * 16 + lr;
#pragma unroll
        for (int nt = 0; nt < 8; nt++) {
            int col = bx * 256 + wn + nt * 8 + 2 * lc;
            float b0 = bias[col], b1 = bias[col + 1];
            float2 v0 = { c[mt][nt][0] + b0, c[mt][nt][1] + b1 };
            float2 v1 = { c[mt][nt][2] + b0, c[mt][nt][3] + b1 };
            *(float2*)(C + (size_t)row * N + col) = v0;
            *(float2*)(C + (size_t)(row + 8) * N + col) = v1;
        }
    }
}

// ---------------- RoPE + logn + split to [b,h,s,d] (Q,K only, tf32-rounded) ----------------
__global__ __launch_bounds__(256) void rope_split(
    const float* __restrict__ qkv,
    const float* __restrict__ cosb, const float* __restrict__ sinb,
    const float* __restrict__ logn,
    float* __restrict__ Q, float* __restrict__ Kt)
{
    int idx = blockIdx.x * blockDim.x + threadIdx.x;   // [b][s][h][d]
    if (idx >= B_ * S_ * NH_ * HD_) return;
    int d = idx & 127;
    int h = (idx >> 7) & 15;
    int s = (idx >> 11) & 2047;
    int b = idx >> 22;

    size_t row = (size_t)(b * S_ + s) * QKV_N;
    int col = h * HD_ + d;

    float cv = cosb[s * HD_ + d];
    float sv = sinb[s * HD_ + d];

    float qv = qkv[row + col];
    float kv = qkv[row + H_ + col];

    int   dro = (d < 64) ? (d + 64) : (d - 64);
    float sgn = (d < 64) ? -1.f : 1.f;
    float qo = qkv[row + h * HD_ + dro];
    float ko = qkv[row + H_ + h * HD_ + dro];

    float qr = qv * cv + sgn * qo * sv;
    float kr = kv * cv + sgn * ko * sv;

    float ln = logn[s] * 0.08838834764831845f;  // fold logn and 1/sqrt(HD) into q

    size_t oidx = (((size_t)(b * NH_ + h) * S_ + s) << 7) + d;
    Q[oidx]  = f2tff(qr * ln);
    Kt[oidx] = f2tff(kr);
}

// ---------------- V transpose: qkv[b,s,h,d] -> Vt[b,h,d,s] (tf32-rounded) ----------------
__global__ __launch_bounds__(256) void vtrans(
    const float* __restrict__ qkv, float* __restrict__ Vt)
{
    __shared__ float t[32][33];
    const int bh = blockIdx.z;
    const int b = bh >> 4, h = bh & 15;
    const int s0 = blockIdx.x * 32, d0 = blockIdx.y * 32;
    const int x = threadIdx.x, y = threadIdx.y;   // 32 x 8

#pragma unroll
    for (int i = 0; i < 32; i += 8)
        t[y + i][x] = qkv[(size_t)(b * S_ + s0 + y + i) * QKV_N + 2 * H_ + h * HD_ + d0 + x];
    __syncthreads();
#pragma unroll
    for (int i = 0; i < 32; i += 8)
        Vt[((size_t)bh * HD_ + d0 + y + i) * S_ + s0 + x] = f2tff(t[x][y + i]);
}

// ---------------- Flash attention: tf32 mma.sync + cp.async + ldmatrix ----------------
#define FBQ 128
#define FBKT 64
#define QSTR 132
#define KSTR 132
#define VSTR 68
#define PSTR 68
#define FK_STG (FBKT * KSTR)
#define OFF_K  (FBQ * QSTR)
#define OFF_V  (OFF_K + 2 * FK_STG)
#define OFF_P  (OFF_V + HD_ * VSTR)
#define FLASH_SMEM ((OFF_P + FBQ * PSTR) * 4)   // 204800 B

__global__ __launch_bounds__(256) void flash_tc(
    const float* __restrict__ Q, const float* __restrict__ K,
    const float* __restrict__ V, float* __restrict__ ctx)
{
    extern __shared__ float fsm[];
    uint32_t* Qs = (uint32_t*)fsm;
    float*    Ks = fsm + OFF_K;
    float*    Vs = fsm + OFF_V;               // [d=128][kv=64] pad->68
    uint32_t* Ps = (uint32_t*)(fsm + OFF_P);
    const uint32_t qs_u = smem_u32(Qs);
    const uint32_t ks_u = smem_u32(Ks);
    const uint32_t vs_u = smem_u32(Vs);
    const uint32_t ps_u = smem_u32(Ps);

    const int qt = (S_ / FBQ - 1) - blockIdx.x;   // heavy tiles first
    const int bh = blockIdx.y;
    const int tid = threadIdx.x;
    const int warp = tid >> 5, lane = tid & 31;
    const int lr = lane >> 2;
    const int lc = lane & 3;

    const int la_m = lane & 15;
    const int la_k = (lane >> 4) << 2;
    const int lb_r = (lane & 7) + ((lane >> 4) << 3);
    const int lb_c = ((lane >> 3) & 1) << 2;

    const uint32_t q_lane = qs_u + (uint32_t)(((warp * 16 + la_m) * QSTR + la_k) * 4);
    const uint32_t p_lane = ps_u + (uint32_t)(((warp * 16 + la_m) * PSTR + la_k) * 4);

    const float* Qb = Q + ((size_t)bh * S_ + qt * FBQ) * HD_;
    const float* Kb = K + (size_t)bh * S_ * HD_;
    const float* Vb = V + (size_t)bh * HD_ * S_;   // [d][s]

    for (int t = tid; t < FBQ * (HD_ / 4); t += 256) {
        int r = t >> 5, c4 = (t & 31) << 2;
        *(uint4*)&Qs[r * QSTR + c4] = *(const uint4*)(Qb + (size_t)r * HD_ + c4);
    }

    const int nkt = 2 * qt + 2;

#define ISSUE_K(kt)                                                               \
    do {                                                                          \
        const float* src = Kb + (size_t)(kt) * FBKT * HD_;                        \
        uint32_t dst = ks_u + (uint32_t)(((kt) & 1) * FK_STG * 4);                \
        _Pragma("unroll")                                                         \
        for (int i = 0; i < 8; i++) {                                             \
            int ch = tid + 256 * i;                                               \
            int r = ch >> 5, c4 = (ch & 31) << 2;                                 \
            cp16(dst + (uint32_t)((r * KSTR + c4) * 4), src + (size_t)r * HD_ + c4); \
        }                                                                         \
    } while (0)
#define ISSUE_V(kt)                                                               \
    do {                                                                          \
        const float* src = Vb + (size_t)(kt) * FBKT;                              \
        _Pragma("unroll")                                                         \
        for (int i = 0; i < 8; i++) {                                             \
            int ch = tid + 256 * i;                                               \
            int r = ch >> 4, c4 = (ch & 15) << 2;                                 \
            cp16(vs_u + (uint32_t)((r * VSTR + c4) * 4), src + (size_t)r * S_ + c4); \
        }                                                                         \
    } while (0)

    ISSUE_K(0);
    cp_commit();

    float m0 = -1e30f, m1 = -1e30f;
    float l0 = 0.f, l1 = 0.f;
    float o[16][4];
#pragma unroll
    for (int nt = 0; nt < 16; nt++)
#pragma unroll
        for (int j = 0; j < 4; j++) o[nt][j] = 0.f;

    const int r0 = warp * 16 + lr;
    const int g0 = qt * FBQ + r0;
    const int g1 = g0 + 8;

    for (int kt = 0; kt < nkt; kt++) {
        ISSUE_V(kt);
        cp_commit();
        if (kt + 1 < nkt) { ISSUE_K(kt + 1); }
        cp_commit();

        cp_wait<2>();
        __syncthreads();

        const uint32_t kst_u = ks_u + (uint32_t)((kt & 1) * FK_STG * 4);

        float s[8][4];
#pragma unroll
        for (int nt = 0; nt < 8; nt++)
#pragma unroll
            for (int j = 0; j < 4; j++) s[nt][j] = 0.f;

#pragma unroll
        for (int ksx = 0; ksx < 16; ksx++) {
            const int kb = ksx * 8;
            uint32_t a[4];
            ldsm4(a, q_lane + (uint32_t)(kb * 4));
#pragma unroll
            for (int p = 0; p < 4; p++) {
                uint32_t r[4];
                ldsm4(r, kst_u + (uint32_t)(((p * 16 + lb_r) * KSTR + kb + lb_c) * 4));
                mma_tf32(s[2 * p], a, r);
                mma_tf32(s[2 * p + 1], a, r + 2);
            }
        }

        if (kt * FBKT + FBKT - 1 > qt * FBQ + warp * 16) {
#pragma unroll
            for (int nt = 0; nt < 8; nt++) {
                int colb = kt * FBKT + nt * 8 + 2 * lc;
                if (colb > g0)     s[nt][0] = -1e30f;
                if (colb + 1 > g0) s[nt][1] = -1e30f;
                if (colb > g1)     s[nt][2] = -1e30f;
                if (colb + 1 > g1) s[nt][3] = -1e30f;
            }
        }

        float mx0 = -1e30f, mx1 = -1e30f;
#pragma unroll
        for (int nt = 0; nt < 8; nt++) {
            mx0 = fmaxf(mx0, fmaxf(s[nt][0], s[nt][1]));
            mx1 = fmaxf(mx1, fmaxf(s[nt][2], s[nt][3]));
        }
        mx0 = fmaxf(mx0, __shfl_xor_sync(0xffffffffu, mx0, 1));
        mx0 = fmaxf(mx0, __shfl_xor_sync(0xffffffffu, mx0, 2));
        mx1 = fmaxf(mx1, __shfl_xor_sync(0xffffffffu, mx1, 1));
        mx1 = fmaxf(mx1, __shfl_xor_sync(0xffffffffu, mx1, 2));

        float nm0 = fmaxf(m0, mx0), nm1 = fmaxf(m1, mx1);
        float al0 = __expf(m0 - nm0), al1 = __expf(m1 - nm1);
        m0 = nm0; m1 = nm1;

        float sum0 = 0.f, sum1 = 0.f;
#pragma unroll
        for (int nt = 0; nt < 8; nt++) {
            s[nt][0] = __expf(s[nt][0] - nm0);
            s[nt][1] = __expf(s[nt][1] - nm0);
            s[nt][2] = __expf(s[nt][2] - nm1);
            s[nt][3] = __expf(s[nt][3] - nm1);
            sum0 += s[nt][0] + s[nt][1];
            sum1 += s[nt][2] + s[nt][3];
        }
        sum0 += __shfl_xor_sync(0xffffffffu, sum0, 1);
        sum0 += __shfl_xor_sync(0xffffffffu, sum0, 2);
        sum1 += __shfl_xor_sync(0xffffffffu, sum1, 1);
        sum1 += __shfl_xor_sync(0xffffffffu, sum1, 2);
        l0 = l0 * al0 + sum0;
        l1 = l1 * al1 + sum1;

#pragma unroll
        for (int nt = 0; nt < 16; nt++) {
            o[nt][0] *= al0; o[nt][1] *= al0;
            o[nt][2] *= al1; o[nt][3] *= al1;
        }

#pragma unroll
        for (int nt = 0; nt < 8; nt++) {
            int colp = nt * 8 + 2 * lc;
            Ps[r0 * PSTR + colp]           = f2tf(s[nt][0]);
            Ps[r0 * PSTR + colp + 1]       = f2tf(s[nt][1]);
            Ps[(r0 + 8) * PSTR + colp]     = f2tf(s[nt][2]);
            Ps[(r0 + 8) * PSTR + colp + 1] = f2tf(s[nt][3]);
        }
        __syncwarp();

        cp_wait<1>();
        __syncthreads();

#pragma unroll
        for (int ksx = 0; ksx < 8; ksx++) {
            const int kb = ksx * 8;
            uint32_t a[4];
            ldsm4(a, p_lane + (uint32_t)(kb * 4));
#pragma unroll
            for (int p = 0; p < 8; p++) {
                uint32_t r[4];
                ldsm4(r, vs_u + (uint32_t)(((p * 16 + lb_r) * VSTR + kb + lb_c) * 4));
                mma_tf32(o[2 * p], a, r);
                mma_tf32(o[2 * p + 1], a, r + 2);
            }
        }
        __syncthreads();
    }
#undef ISSUE_K
#undef ISSUE_V

    float il0 = 1.f / l0, il1 = 1.f / l1;
    int b = bh >> 4, h = bh & 15;
    float* out0 = ctx + (size_t)(b * S_ + g0) * H_ + h * HD_;
    float* out1 = ctx + (size_t)(b * S_ + g1) * H_ + h * HD_;
#pragma unroll
    for (int nt = 0; nt < 16; nt++) {
        int col = nt * 8 + 2 * lc;
        float2 v0 = { f2tff(o[nt][0] * il0), f2tff(o[nt][1] * il0) };
        float2 v1 = { f2tff(o[nt][2] * il1), f2tff(o[nt][3] * il1) };
        *(float2*)(out0 + col) = v0;
        *(float2*)(out1 + col) = v1;
    }
}

// ---------------- launch ----------------
extern "C" void kernel_launch(void* const* d_in, const int* in_sizes, int n_in,
                              void* d_out, int out_size)
{
    const float* hidden = (const float*)d_in[0];
    const float* cosb   = (const float*)d_in[1];
    const float* sinb   = (const float*)d_in[2];
    // d_in[3]: attention_mask (pure causal -> implemented directly)
    const float* logn   = (const float*)d_in[4];
    const float* Wc     = (const float*)d_in[5];
    const float* bc     = (const float*)d_in[6];
    const float* Wp     = (const float*)d_in[7];
    const float* bp     = (const float*)d_in[8];
    float* out = (float*)d_out;

    float *qkv, *Q, *Kt, *Vt, *ctx, *hid_tf, *wct, *wpt;
    cudaGetSymbolAddress((void**)&qkv,    g_qkv);
    cudaGetSymbolAddress((void**)&Q,      g_q);
    cudaGetSymbolAddress((void**)&Kt,     g_k);
    cudaGetSymbolAddress((void**)&Vt,     g_v);
    cudaGetSymbolAddress((void**)&ctx,    g_ctx);
    cudaGetSymbolAddress((void**)&hid_tf, g_hid_tf);
    cudaGetSymbolAddress((void**)&wct,    g_wct);
    cudaGetSymbolAddress((void**)&wpt,    g_wpt);

    cudaFuncSetAttribute(gemm_tf32,
                         cudaFuncAttributeMaxDynamicSharedMemorySize, GEMM_SMEM);
    cudaFuncSetAttribute(flash_tc,
                         cudaFuncAttributeMaxDynamicSharedMemorySize, FLASH_SMEM);

    // 0) pre-round A; transpose+round weights to [N][K]
    {
        int n4h = (ROWS_ * H_) / 4;
        to_tf32k<<<(n4h + 255) / 256, 256>>>(hidden, hid_tf, n4h);
        wtrans<<<dim3(H_ / 32, QKV_N / 32), dim3(32, 8)>>>(Wc, wct, H_, QKV_N);
        wtrans<<<dim3(H_ / 32, H_ / 32), dim3(32, 8)>>>(Wp, wpt, H_, H_);
    }

    // 1) qkv = hidden @ Wc + bc   [4096,6144]
    gemm_tf32<<<dim3(QKV_N / 256, ROWS_ / 128), 256, GEMM_SMEM>>>(
        hid_tf, wct, bc, qkv, ROWS_, QKV_N, H_);

    // 2) rope + logn -> Q,K [b,h,s,d];  V transpose -> [b,h,d,s]
    {
        int total = B_ * S_ * NH_ * HD_;
        rope_split<<<(total + 255) / 256, 256>>>(qkv, cosb, sinb, logn, Q, Kt);
        vtrans<<<dim3(S_ / 32, HD_ / 32, B_ * NH_), dim3(32, 8)>>>(qkv, Vt);
    }

    // 3) flash attention -> ctx [4096, 2048]
    flash_tc<<<dim3(S_ / FBQ, B_ * NH_), 256, FLASH_SMEM>>>(Q, Kt, Vt, ctx);

    // 4) out = ctx @ Wp + bp      [4096,2048]
    gemm_tf32<<<dim3(H_ / 256, ROWS_ / 128), 256, GEMM_SMEM>>>(
        ctx, wpt, bp, out, ROWS_, H_, H_);
}

// round 7
// speedup vs baseline: 1.1701x; 1.1701x over previous
#include <cuda_runtime.h>
#include <cuda_bf16.h>
#include <math.h>
#include <stdint.h>

// Problem constants
#define B_  2
#define S_  2048
#define H_  2048
#define NH_ 16
#define HD_ 128
#define ROWS_ (B_ * S_)        // 4096
#define QKV_N (3 * H_)         // 6144

// ---------------- scratch (static device globals; no allocation) ----------------
__device__ float g_qkv[(size_t)ROWS_ * QKV_N];            // [4096, 6144]
__device__ float g_q[(size_t)B_ * NH_ * S_ * HD_];        // [b,h,s,d] tf32-rounded
__device__ float g_k[(size_t)B_ * NH_ * S_ * HD_];        // [b,h,s,d] tf32-rounded
__device__ float g_v[(size_t)B_ * NH_ * S_ * HD_];        // [b,h,d,s] tf32-rounded
__device__ float g_ctx[(size_t)ROWS_ * H_];               // [b*s, h*d] tf32-rounded
__device__ float g_hid_tf[(size_t)ROWS_ * H_];            // tf32-rounded A
__device__ float g_wct[(size_t)QKV_N * H_];               // Wc^T [6144][2048] tf32
__device__ float g_wpt[(size_t)H_ * H_];                  // Wp^T [2048][2048] tf32

// ---------------- helpers ----------------
__device__ __forceinline__ uint32_t f2tf(float x) {
    uint32_t r;
    asm("cvt.rna.tf32.f32 %0, %1;" : "=r"(r) : "f"(x));
    return r;
}
__device__ __forceinline__ float f2tff(float x) { return __uint_as_float(f2tf(x)); }

__device__ __forceinline__ void mma_tf32(float* c, const uint32_t* a, const uint32_t* b) {
    asm volatile(
        "mma.sync.aligned.m16n8k8.row.col.f32.tf32.tf32.f32 "
        "{%0,%1,%2,%3}, {%4,%5,%6,%7}, {%8,%9}, {%0,%1,%2,%3};\n"
        : "+f"(c[0]), "+f"(c[1]), "+f"(c[2]), "+f"(c[3])
        : "r"(a[0]), "r"(a[1]), "r"(a[2]), "r"(a[3]),
          "r"(b[0]), "r"(b[1]));
}
__device__ __forceinline__ void ldsm4(uint32_t* r, uint32_t addr) {
    asm volatile("ldmatrix.sync.aligned.m8n8.x4.shared.b16 {%0,%1,%2,%3}, [%4];"
        : "=r"(r[0]), "=r"(r[1]), "=r"(r[2]), "=r"(r[3]) : "r"(addr));
}
__device__ __forceinline__ uint32_t smem_u32(const void* p) {
    return (uint32_t)__cvta_generic_to_shared(p);
}
__device__ __forceinline__ void cp16(uint32_t dst, const void* src) {
    asm volatile("cp.async.cg.shared.global [%0], [%1], 16;" :: "r"(dst), "l"(src));
}
__device__ __forceinline__ void cp_commit() {
    asm volatile("cp.async.commit_group;");
}
template<int N> __device__ __forceinline__ void cp_wait() {
    asm volatile("cp.async.wait_group %0;" :: "n"(N));
}

// ---------------- tf32 pre-round (elementwise) ----------------
__global__ __launch_bounds__(256) void to_tf32k(const float* __restrict__ in,
                                                float* __restrict__ out, int n4)
{
    int i = blockIdx.x * 256 + threadIdx.x;
    if (i < n4) {
        float4 v = ((const float4*)in)[i];
        v.x = f2tff(v.x); v.y = f2tff(v.y); v.z = f2tff(v.z); v.w = f2tff(v.w);
        ((float4*)out)[i] = v;
    }
}

// ---------------- weight transpose + round: in[K][N] -> out[N][K] ----------------
__global__ __launch_bounds__(256) void wtrans(
    const float* __restrict__ in, float* __restrict__ out, int K, int N)
{
    __shared__ float t[32][33];
    const int k0 = blockIdx.x * 32, n0 = blockIdx.y * 32;
    const int x = threadIdx.x, y = threadIdx.y;   // 32 x 8
#pragma unroll
    for (int i = 0; i < 32; i += 8)
        t[y + i][x] = in[(size_t)(k0 + y + i) * N + n0 + x];
    __syncthreads();
#pragma unroll
    for (int i = 0; i < 32; i += 8)
        out[(size_t)(n0 + y + i) * K + k0 + x] = f2tff(t[x][y + i]);
}

// ---------------- TF32 GEMM: C[M,N] = A[M,K] @ Bt[N,K]^T + bias ----------------
// CTA tile 128x128, BK=32, 3 stages, 256 threads (8 warps, 2m x 4n), warp m64 x n32.
// As/Bs: [128][36] per stage, k-minor -> all fragments via ldmatrix, conflict-free.
#define GSTR 36
#define GT_ST (128 * GSTR)          // 4608 words per operand per stage
#define G_ST  (2 * GT_ST)           // 9216 words per stage
#define GEMM_SMEM (3 * G_ST * 4)    // 110592 B

__global__ __launch_bounds__(256) void gemm_tf32(
    const float* __restrict__ A, const float* __restrict__ Bt,
    const float* __restrict__ bias, float* __restrict__ C,
    int M, int N, int K)
{
    extern __shared__ float gsm[];
    const uint32_t as_u = smem_u32(gsm);

    const int tid = threadIdx.x;
    const int bx = blockIdx.x, by = blockIdx.y;
    const int warp = tid >> 5, lane = tid & 31;
    const int wm = (warp & 1) * 64;       // 2 warps in m
    const int wn = (warp >> 1) * 32;      // 4 warps in n
    const int lr = lane >> 2;
    const int lc = lane & 3;

    // ldmatrix lane geometry
    const int la_m = lane & 15;
    const int la_k = (lane >> 4) << 2;
    const int lb_r = (lane & 7) + ((lane >> 4) << 3);
    const int lb_c = ((lane >> 3) & 1) << 2;

    const uint32_t a_lane = as_u + (uint32_t)(((wm + la_m) * GSTR + la_k) * 4);
    const uint32_t b_lane = as_u + (uint32_t)(GT_ST * 4)
                          + (uint32_t)(((wn + lb_r) * GSTR + lb_c) * 4);

    const float* Ab = A + (size_t)(by * 128) * K;
    const float* Bb = Bt + (size_t)(bx * 128) * K;

    const int KT = K >> 5;   // k32 chunks

    // fill one k32 tile into stage st: A 128x32 + B 128x32 (1024 chunks each)
#define ISSUE_TILE(kt, st)                                                        \
    do {                                                                          \
        const float* Asrc = Ab + (kt) * 32;                                       \
        const float* Bsrc = Bb + (kt) * 32;                                       \
        uint32_t au = as_u + (uint32_t)((st) * G_ST * 4);                         \
        uint32_t bu = au + (uint32_t)(GT_ST * 4);                                 \
        _Pragma("unroll")                                                         \
        for (int i = 0; i < 4; i++) {                                             \
            int ch = tid + 256 * i;                                               \
            int r = ch >> 3, c = (ch & 7) << 2;                                   \
            cp16(au + (uint32_t)((r * GSTR + c) * 4), Asrc + (size_t)r * K + c);  \
            cp16(bu + (uint32_t)((r * GSTR + c) * 4), Bsrc + (size_t)r * K + c);  \
        }                                                                         \
    } while (0)

    ISSUE_TILE(0, 0); cp_commit();
    ISSUE_TILE(1, 1); cp_commit();

    float c[4][4][4];
#pragma unroll
    for (int mt = 0; mt < 4; mt++)
#pragma unroll
        for (int nt = 0; nt < 4; nt++)
#pragma unroll
            for (int j = 0; j < 4; j++) c[mt][nt][j] = 0.f;

    for (int kt = 0; kt < KT; kt++) {
        cp_wait<1>();        // stage kt resident
        __syncthreads();
        if (kt + 2 < KT) { ISSUE_TILE(kt + 2, (kt + 2) % 3); }
        cp_commit();

        const uint32_t stoff = (uint32_t)((kt % 3) * G_ST * 4);
        const uint32_t a_st = a_lane + stoff;
        const uint32_t b_st = b_lane + stoff;

#pragma unroll
        for (int ks = 0; ks < 4; ks++) {
            const int kb = ks * 8;
            uint32_t af[4][4], bf[4][2];
#pragma unroll
            for (int mt = 0; mt < 4; mt++)
                ldsm4(af[mt], a_st + (uint32_t)((mt * 16 * GSTR + kb) * 4));
#pragma unroll
            for (int p = 0; p < 2; p++) {
                uint32_t r[4];
                ldsm4(r, b_st + (uint32_t)((p * 16 * GSTR + kb) * 4));
                bf[2 * p][0] = r[0]; bf[2 * p][1] = r[1];
                bf[2 * p + 1][0] = r[2]; bf[2 * p + 1][1] = r[3];
            }
#pragma unroll
            for (int mt = 0; mt < 4; mt++)
#pragma unroll
                for (int nt = 0; nt < 4; nt++)
                    mma_tf32(c[mt][nt], af[mt], bf[nt]);
        }
    }
#undef ISSUE_TILE

    // epilogue
#pragma unroll
    for (int mt = 0; mt < 4; mt++) {
        int row = by * 128 + wm + mt * 16 + lr;
#pragma unroll
        for (int nt = 0; nt < 4; nt++) {
            int col = bx * 128 + wn + nt * 8 + 2 * lc;
            float b0 = bias[col], b1 = bias[col + 1];
            float2 v0 = { c[mt][nt][0] + b0, c[mt][nt][1] + b1 };
            float2 v1 = { c[mt][nt][2] + b0, c[mt][nt][3] + b1 };
            *(float2*)(C + (size_t)row * N + col) = v0;
            *(float2*)(C + (size_t)(row + 8) * N + col) = v1;
        }
    }
}

// ---------------- RoPE + logn + split to [b,h,s,d] (Q,K only, tf32-rounded) ----------------
__global__ __launch_bounds__(256) void rope_split(
    const float* __restrict__ qkv,
    const float* __restrict__ cosb, const float* __restrict__ sinb,
    const float* __restrict__ logn,
    float* __restrict__ Q, float* __restrict__ Kt)
{
    int idx = blockIdx.x * blockDim.x + threadIdx.x;   // [b][s][h][d]
    if (idx >= B_ * S_ * NH_ * HD_) return;
    int d = idx & 127;
    int h = (idx >> 7) & 15;
    int s = (idx >> 11) & 2047;
    int b = idx >> 22;

    size_t row = (size_t)(b * S_ + s) * QKV_N;
    int col = h * HD_ + d;

    float cv = cosb[s * HD_ + d];
    float sv = sinb[s * HD_ + d];

    float qv = qkv[row + col];
    float kv = qkv[row + H_ + col];

    int   dro = (d < 64) ? (d + 64) : (d - 64);
    float sgn = (d < 64) ? -1.f : 1.f;
    float qo = qkv[row + h * HD_ + dro];
    float ko = qkv[row + H_ + h * HD_ + dro];

    float qr = qv * cv + sgn * qo * sv;
    float kr = kv * cv + sgn * ko * sv;

    float ln = logn[s] * 0.08838834764831845f;  // fold logn and 1/sqrt(HD) into q

    size_t oidx = (((size_t)(b * NH_ + h) * S_ + s) << 7) + d;
    Q[oidx]  = f2tff(qr * ln);
    Kt[oidx] = f2tff(kr);
}

// ---------------- V transpose: qkv[b,s,h,d] -> Vt[b,h,d,s] (tf32-rounded) ----------------
__global__ __launch_bounds__(256) void vtrans(
    const float* __restrict__ qkv, float* __restrict__ Vt)
{
    __shared__ float t[32][33];
    const int bh = blockIdx.z;
    const int b = bh >> 4, h = bh & 15;
    const int s0 = blockIdx.x * 32, d0 = blockIdx.y * 32;
    const int x = threadIdx.x, y = threadIdx.y;   // 32 x 8

#pragma unroll
    for (int i = 0; i < 32; i += 8)
        t[y + i][x] = qkv[(size_t)(b * S_ + s0 + y + i) * QKV_N + 2 * H_ + h * HD_ + d0 + x];
    __syncthreads();
#pragma unroll
    for (int i = 0; i < 32; i += 8)
        Vt[((size_t)bh * HD_ + d0 + y + i) * S_ + s0 + x] = f2tff(t[x][y + i]);
}

// ---------------- Flash attention: tf32 mma.sync + cp.async + ldmatrix ----------------
#define FBQ 128
#define FBKT 64
#define QSTR 132
#define KSTR 132
#define VSTR 68
#define PSTR 68
#define FK_STG (FBKT * KSTR)
#define OFF_K  (FBQ * QSTR)
#define OFF_V  (OFF_K + 2 * FK_STG)
#define OFF_P  (OFF_V + HD_ * VSTR)
#define FLASH_SMEM ((OFF_P + FBQ * PSTR) * 4)   // 204800 B

__global__ __launch_bounds__(256) void flash_tc(
    const float* __restrict__ Q, const float* __restrict__ K,
    const float* __restrict__ V, float* __restrict__ ctx)
{
    extern __shared__ float fsm[];
    uint32_t* Qs = (uint32_t*)fsm;
    float*    Ks = fsm + OFF_K;
    float*    Vs = fsm + OFF_V;               // [d=128][kv=64] pad->68
    uint32_t* Ps = (uint32_t*)(fsm + OFF_P);
    const uint32_t qs_u = smem_u32(Qs);
    const uint32_t ks_u = smem_u32(Ks);
    const uint32_t vs_u = smem_u32(Vs);
    const uint32_t ps_u = smem_u32(Ps);

    const int qt = (S_ / FBQ - 1) - blockIdx.x;   // heavy tiles first
    const int bh = blockIdx.y;
    const int tid = threadIdx.x;
    const int warp = tid >> 5, lane = tid & 31;
    const int lr = lane >> 2;
    const int lc = lane & 3;

    const int la_m = lane & 15;
    const int la_k = (lane >> 4) << 2;
    const int lb_r = (lane & 7) + ((lane >> 4) << 3);
    const int lb_c = ((lane >> 3) & 1) << 2;

    const uint32_t q_lane = qs_u + (uint32_t)(((warp * 16 + la_m) * QSTR + la_k) * 4);
    const uint32_t p_lane = ps_u + (uint32_t)(((warp * 16 + la_m) * PSTR + la_k) * 4);

    const float* Qb = Q + ((size_t)bh * S_ + qt * FBQ) * HD_;
    const float* Kb = K + (size_t)bh * S_ * HD_;
    const float* Vb = V + (size_t)bh * HD_ * S_;   // [d][s]

    for (int t = tid; t < FBQ * (HD_ / 4); t += 256) {
        int r = t >> 5, c4 = (t & 31) << 2;
        *(uint4*)&Qs[r * QSTR + c4] = *(const uint4*)(Qb + (size_t)r * HD_ + c4);
    }

    const int nkt = 2 * qt + 2;

#define ISSUE_K(kt)                                                               \
    do {                                                                          \
        const float* src = Kb + (size_t)(kt) * FBKT * HD_;                        \
        uint32_t dst = ks_u + (uint32_t)(((kt) & 1) * FK_STG * 4);                \
        _Pragma("unroll")                                                         \
        for (int i = 0; i < 8; i++) {                                             \
            int ch = tid + 256 * i;                                               \
            int r = ch >> 5, c4 = (ch & 31) << 2;                                 \
            cp16(dst + (uint32_t)((r * KSTR + c4) * 4), src + (size_t)r * HD_ + c4); \
        }                                                                         \
    } while (0)
#define ISSUE_V(kt)                                                               \
    do {                                                                          \
        const float* src = Vb + (size_t)(kt) * FBKT;                              \
        _Pragma("unroll")                                                         \
        for (int i = 0; i < 8; i++) {                                             \
            int ch = tid + 256 * i;                                               \
            int r = ch >> 4, c4 = (ch & 15) << 2;                                 \
            cp16(vs_u + (uint32_t)((r * VSTR + c4) * 4), src + (size_t)r * S_ + c4); \
        }                                                                         \
    } while (0)

    ISSUE_K(0);
    cp_commit();

    float m0 = -1e30f, m1 = -1e30f;
    float l0 = 0.f, l1 = 0.f;
    float o[16][4];
#pragma unroll
    for (int nt = 0; nt < 16; nt++)
#pragma unroll
        for (int j = 0; j < 4; j++) o[nt][j] = 0.f;

    const int r0 = warp * 16 + lr;
    const int g0 = qt * FBQ + r0;
    const int g1 = g0 + 8;

    for (int kt = 0; kt < nkt; kt++) {
        ISSUE_V(kt);
        cp_commit();
        if (kt + 1 < nkt) { ISSUE_K(kt + 1); }
        cp_commit();

        cp_wait<2>();
        __syncthreads();

        const uint32_t kst_u = ks_u + (uint32_t)((kt & 1) * FK_STG * 4);

        float s[8][4];
#pragma unroll
        for (int nt = 0; nt < 8; nt++)
#pragma unroll
            for (int j = 0; j < 4; j++) s[nt][j] = 0.f;

#pragma unroll
        for (int ksx = 0; ksx < 16; ksx++) {
            const int kb = ksx * 8;
            uint32_t a[4];
            ldsm4(a, q_lane + (uint32_t)(kb * 4));
#pragma unroll
            for (int p = 0; p < 4; p++) {
                uint32_t r[4];
                ldsm4(r, kst_u + (uint32_t)(((p * 16 + lb_r) * KSTR + kb + lb_c) * 4));
                mma_tf32(s[2 * p], a, r);
                mma_tf32(s[2 * p + 1], a, r + 2);
            }
        }

        if (kt * FBKT + FBKT - 1 > qt * FBQ + warp * 16) {
#pragma unroll
            for (int nt = 0; nt < 8; nt++) {
                int colb = kt * FBKT + nt * 8 + 2 * lc;
                if (colb > g0)     s[nt][0] = -1e30f;
                if (colb + 1 > g0) s[nt][1] = -1e30f;
                if (colb > g1)     s[nt][2] = -1e30f;
                if (colb + 1 > g1) s[nt][3] = -1e30f;
            }
        }

        float mx0 = -1e30f, mx1 = -1e30f;
#pragma unroll
        for (int nt = 0; nt < 8; nt++) {
            mx0 = fmaxf(mx0, fmaxf(s[nt][0], s[nt][1]));
            mx1 = fmaxf(mx1, fmaxf(s[nt][2], s[nt][3]));
        }
        mx0 = fmaxf(mx0, __shfl_xor_sync(0xffffffffu, mx0, 1));
        mx0 = fmaxf(mx0, __shfl_xor_sync(0xffffffffu, mx0, 2));
        mx1 = fmaxf(mx1, __shfl_xor_sync(0xffffffffu, mx1, 1));
        mx1 = fmaxf(mx1, __shfl_xor_sync(0xffffffffu, mx1, 2));

        float nm0 = fmaxf(m0, mx0), nm1 = fmaxf(m1, mx1);
        float al0 = __expf(m0 - nm0), al1 = __expf(m1 - nm1);
        m0 = nm0; m1 = nm1;

        float sum0 = 0.f, sum1 = 0.f;
#pragma unroll
        for (int nt = 0; nt < 8; nt++) {
            s[nt][0] = __expf(s[nt][0] - nm0);
            s[nt][1] = __expf(s[nt][1] - nm0);
            s[nt][2] = __expf(s[nt][2] - nm1);
            s[nt][3] = __expf(s[nt][3] - nm1);
            sum0 += s[nt][0] + s[nt][1];
            sum1 += s[nt][2] + s[nt][3];
        }
        sum0 += __shfl_xor_sync(0xffffffffu, sum0, 1);
        sum0 += __shfl_xor_sync(0xffffffffu, sum0, 2);
        sum1 += __shfl_xor_sync(0xffffffffu, sum1, 1);
        sum1 += __shfl_xor_sync(0xffffffffu, sum1, 2);
        l0 = l0 * al0 + sum0;
        l1 = l1 * al1 + sum1;

#pragma unroll
        for (int nt = 0; nt < 16; nt++) {
            o[nt][0] *= al0; o[nt][1] *= al0;
            o[nt][2] *= al1; o[nt][3] *= al1;
        }

#pragma unroll
        for (int nt = 0; nt < 8; nt++) {
            int colp = nt * 8 + 2 * lc;
            Ps[r0 * PSTR + colp]           = f2tf(s[nt][0]);
            Ps[r0 * PSTR + colp + 1]       = f2tf(s[nt][1]);
            Ps[(r0 + 8) * PSTR + colp]     = f2tf(s[nt][2]);
            Ps[(r0 + 8) * PSTR + colp + 1] = f2tf(s[nt][3]);
        }
        __syncwarp();

        cp_wait<1>();
        __syncthreads();

#pragma unroll
        for (int ksx = 0; ksx < 8; ksx++) {
            const int kb = ksx * 8;
            uint32_t a[4];
            ldsm4(a, p_lane + (uint32_t)(kb * 4));
#pragma unroll
            for (int p = 0; p < 8; p++) {
                uint32_t r[4];
                ldsm4(r, vs_u + (uint32_t)(((p * 16 + lb_r) * VSTR + kb + lb_c) * 4));
                mma_tf32(o[2 * p], a, r);
                mma_tf32(o[2 * p + 1], a, r + 2);
            }
        }
        __syncthreads();
    }
#undef ISSUE_K
#undef ISSUE_V

    float il0 = 1.f / l0, il1 = 1.f / l1;
    int b = bh >> 4, h = bh & 15;
    float* out0 = ctx + (size_t)(b * S_ + g0) * H_ + h * HD_;
    float* out1 = ctx + (size_t)(b * S_ + g1) * H_ + h * HD_;
#pragma unroll
    for (int nt = 0; nt < 16; nt++) {
        int col = nt * 8 + 2 * lc;
        float2 v0 = { f2tff(o[nt][0] * il0), f2tff(o[nt][1] * il0) };
        float2 v1 = { f2tff(o[nt][2] * il1), f2tff(o[nt][3] * il1) };
        *(float2*)(out0 + col) = v0;
        *(float2*)(out1 + col) = v1;
    }
}

// ---------------- launch ----------------
extern "C" void kernel_launch(void* const* d_in, const int* in_sizes, int n_in,
                              void* d_out, int out_size)
{
    const float* hidden = (const float*)d_in[0];
    const float* cosb   = (const float*)d_in[1];
    const float* sinb   = (const float*)d_in[2];
    // d_in[3]: attention_mask (pure causal -> implemented directly)
    const float* logn   = (const float*)d_in[4];
    const float* Wc     = (const float*)d_in[5];
    const float* bc     = (const float*)d_in[6];
    const float* Wp     = (const float*)d_in[7];
    const float* bp     = (const float*)d_in[8];
    float* out = (float*)d_out;

    float *qkv, *Q, *Kt, *Vt, *ctx, *hid_tf, *wct, *wpt;
    cudaGetSymbolAddress((void**)&qkv,    g_qkv);
    cudaGetSymbolAddress((void**)&Q,      g_q);
    cudaGetSymbolAddress((void**)&Kt,     g_k);
    cudaGetSymbolAddress((void**)&Vt,     g_v);
    cudaGetSymbolAddress((void**)&ctx,    g_ctx);
    cudaGetSymbolAddress((void**)&hid_tf, g_hid_tf);
    cudaGetSymbolAddress((void**)&wct,    g_wct);
    cudaGetSymbolAddress((void**)&wpt,    g_wpt);

    cudaFuncSetAttribute(gemm_tf32,
                         cudaFuncAttributeMaxDynamicSharedMemorySize, GEMM_SMEM);
    cudaFuncSetAttribute(flash_tc,
                         cudaFuncAttributeMaxDynamicSharedMemorySize, FLASH_SMEM);

    // 0) pre-round A; transpose+round weights to [N][K]
    {
        int n4h = (ROWS_ * H_) / 4;
        to_tf32k<<<(n4h + 255) / 256, 256>>>(hidden, hid_tf, n4h);
        wtrans<<<dim3(H_ / 32, QKV_N / 32), dim3(32, 8)>>>(Wc, wct, H_, QKV_N);
        wtrans<<<dim3(H_ / 32, H_ / 32), dim3(32, 8)>>>(Wp, wpt, H_, H_);
    }

    // 1) qkv = hidden @ Wc + bc   [4096,6144]
    gemm_tf32<<<dim3(QKV_N / 128, ROWS_ / 128), 256, GEMM_SMEM>>>(
        hid_tf, wct, bc, qkv, ROWS_, QKV_N, H_);

    // 2) rope + logn -> Q,K [b,h,s,d];  V transpose -> [b,h,d,s]
    {
        int total = B_ * S_ * NH_ * HD_;
        rope_split<<<(total + 255) / 256, 256>>>(qkv, cosb, sinb, logn, Q, Kt);
        vtrans<<<dim3(S_ / 32, HD_ / 32, B_ * NH_), dim3(32, 8)>>>(qkv, Vt);
    }

    // 3) flash attention -> ctx [4096, 2048]
    flash_tc<<<dim3(S_ / FBQ, B_ * NH_), 256, FLASH_SMEM>>>(Q, Kt, Vt, ctx);

    // 4) out = ctx @ Wp + bp      [4096,2048]
    gemm_tf32<<<dim3(H_ / 128, ROWS_ / 128), 256, GEMM_SMEM>>>(
        ctx, wpt, bp, out, ROWS_, H_, H_);
}